// round 14
// baseline (speedup 1.0000x reference)
#include <cuda_runtime.h>
#include <cuda_bf16.h>
#include <math.h>
#include <stdint.h>

#define NB 64
#define NV 50000
#define M_ROWS (NV*3)   // 150000
#define KS 300
#define KP 207
#define PDW 112         // padded posedirs row length in bf16-pair words

typedef unsigned long long ull;

__constant__ int c_parent[23] = {0,0,0,1,2,3,4,5,6,7,8,9,9,9,12,13,14,16,17,18,19,20,21};

// Scratch (device globals; no allocation allowed)
__device__ float g_R[NB*24*9];
__device__ float g_lrot[NB*KP];
__device__ float g_vshaped[M_ROWS*NB];     // [row][b]
__device__ float g_vposed[M_ROWS*NB];      // [row][b]
__device__ float g_J[NB*72];
__device__ float g_Gpair[NB*288];          // pair-packed G
__device__ uint32_t g_pdw[M_ROWS*PDW];     // posedirs as bf16-pair words, padded
#define NBLK_J 256
__device__ float g_Jpart[NBLK_J*4608];

// -------- helpers --------
__device__ __forceinline__ uint32_t pk_bf16(float lo, float hi) {
    __nv_bfloat162 h = __floats2bfloat162_rn(lo, hi);
    return *(uint32_t*)&h;
}
__device__ __forceinline__ uint32_t smem_u32(const void* p) {
    return (uint32_t)__cvta_generic_to_shared(p);
}
__device__ __forceinline__ void ldsm4(uint32_t* r, uint32_t addr) {
    asm volatile("ldmatrix.sync.aligned.m8n8.x4.shared.b16 {%0,%1,%2,%3}, [%4];"
        : "=r"(r[0]), "=r"(r[1]), "=r"(r[2]), "=r"(r[3]) : "r"(addr));
}
__device__ __forceinline__ void mma_bf16(float* d,
                                         const uint32_t* a,
                                         const uint32_t* b) {
    asm volatile(
        "mma.sync.aligned.m16n8k16.row.col.f32.bf16.bf16.f32 "
        "{%0,%1,%2,%3}, {%4,%5,%6,%7}, {%8,%9}, {%0,%1,%2,%3};\n"
        : "+f"(d[0]), "+f"(d[1]), "+f"(d[2]), "+f"(d[3])
        : "r"(a[0]), "r"(a[1]), "r"(a[2]), "r"(a[3]),
          "r"(b[0]), "r"(b[1]));
}
__device__ __forceinline__ ull pk2(float lo, float hi) {
    ull r;
    asm("mov.b64 %0, {%1,%2};" : "=l"(r) : "f"(lo), "f"(hi));
    return r;
}
__device__ __forceinline__ void fma2(ull& d, ull a, ull b) {
    asm("fma.rn.f32x2 %0, %1, %2, %0;" : "+l"(d) : "l"(a), "l"(b));
}
__device__ __forceinline__ void unpk2(float& lo, float& hi, ull v) {
    asm("mov.b64 {%0,%1}, %2;" : "=f"(lo), "=f"(hi) : "l"(v));
}

// ---------------- K0: posedirs fp32 -> bf16-pair words (padded rows) ----------------
__global__ __launch_bounds__(256) void k_pdcvt(const float* __restrict__ pd) {
    int idx = blockIdx.x * 256 + threadIdx.x;
    if (idx < M_ROWS * PDW) {
        int r = idx / PDW, w = idx % PDW;
        int k = 2*w;
        float f0 = (k < KP)     ? pd[(size_t)r*KP + k]     : 0.f;
        float f1 = (k+1 < KP)   ? pd[(size_t)r*KP + k + 1] : 0.f;
        g_pdw[idx] = pk_bf16(f0, f1);
    }
}

// ---------------- K1: rodrigues -> R, lrotmin ----------------
__global__ void k_pose(const float* __restrict__ pose) {
    int b = blockIdx.x;
    int j = threadIdx.x;
    if (j < 24) {
        float t0 = pose[b*72 + j*3 + 0];
        float t1 = pose[b*72 + j*3 + 1];
        float t2 = pose[b*72 + j*3 + 2];
        float a0 = t0 + 1e-8f, a1 = t1 + 1e-8f, a2 = t2 + 1e-8f;
        float ang = sqrtf(a0*a0 + a1*a1 + a2*a2);
        float inv = 1.0f/ang;
        float half = 0.5f*ang;
        float s = sinf(half), c = cosf(half);
        float qw = c, qx = s*t0*inv, qy = s*t1*inv, qz = s*t2*inv;
        float qn = rsqrtf(qw*qw + qx*qx + qy*qy + qz*qz);
        qw *= qn; qx *= qn; qy *= qn; qz *= qn;
        float R[9];
        R[0] = qw*qw + qx*qx - qy*qy - qz*qz;
        R[1] = 2.f*(qx*qy - qw*qz);
        R[2] = 2.f*(qw*qy + qx*qz);
        R[3] = 2.f*(qw*qz + qx*qy);
        R[4] = qw*qw - qx*qx + qy*qy - qz*qz;
        R[5] = 2.f*(qy*qz - qw*qx);
        R[6] = 2.f*(qx*qz - qw*qy);
        R[7] = 2.f*(qw*qx + qy*qz);
        R[8] = qw*qw - qx*qx - qy*qy + qz*qz;
        #pragma unroll
        for (int e = 0; e < 9; e++) g_R[b*216 + j*9 + e] = R[e];
        if (j >= 1) {
            #pragma unroll
            for (int e = 0; e < 9; e++) {
                float d = (e == 0 || e == 4 || e == 8) ? 1.0f : 0.0f;
                g_lrot[b*207 + (j-1)*9 + e] = R[e] - d;
            }
        }
    }
}

// ======== shared fragment-address helpers (stride 20 words, conflict-free) ========
// A tile: [128][20] words; B tile: [64][20] words.

// ---------------- K2: v_shaped GEMM, bf16 MMA + ldmatrix ----------------
#define KT 32
#define NT2 ((KS + KT - 1) / KT)   // 10
#define ABUF_W (128*20)
#define BBUF_W (64*20)
__global__ __launch_bounds__(256, 3) void k_shape(const float* __restrict__ sd,
                                                  const float* __restrict__ beta,
                                                  const float* __restrict__ vt) {
    __shared__ uint32_t As[2][ABUF_W];
    __shared__ uint32_t Bs[2][BBUF_W];
    int tid = threadIdx.x;
    int warp = tid >> 5, lane = tid & 31;
    int gid = lane >> 2, tg = lane & 3;
    int wm = warp >> 1, wn = warp & 1;
    int row0 = blockIdx.x * 128;

    int ra = tid >> 1, ha = tid & 1;
    bool rowokA = (row0 + ra) < M_ROWS;
    const float* srowA = sd + (size_t)(rowokA ? (row0 + ra) : 0) * KS;
    int bb = tid >> 2, kq = tid & 3;

    // ldmatrix addresses (buf 0); buf1 = +buffer bytes
    uint32_t addrA[2], addrB[2];
    {
        int rA = (lane & 7) + (lane & 8);
        int wA = (lane & 16) >> 2;          // 0 or 4 words
        addrA[0] = smem_u32(&As[0][(wm*32 + 0*16 + rA)*20 + wA]);
        addrA[1] = smem_u32(&As[0][(wm*32 + 1*16 + rA)*20 + wA]);
        int nB0 = wn*32 + ((lane & 16) >> 1) + (lane & 7);   // nh=0: +0 or +8 rows
        int wB = (lane & 8) >> 1;           // 0 or 4 words
        addrB[0] = smem_u32(&Bs[0][nB0*20 + wB]);
        addrB[1] = smem_u32(&Bs[0][(nB0 + 16)*20 + wB]);
    }

    uint32_t aW[8], bW[4];
    #pragma unroll
    for (int q = 0; q < 4; q++) {
        int kk = ha*16 + q*4;
        float4 v = (rowokA && kk < KS) ? *(const float4*)(srowA + kk)
                                       : make_float4(0.f,0.f,0.f,0.f);
        aW[q*2]   = pk_bf16(v.x, v.y);
        aW[q*2+1] = pk_bf16(v.z, v.w);
    }
    #pragma unroll
    for (int q = 0; q < 2; q++) {
        int kk = kq*8 + q*4;
        float4 v = (kk < KS) ? *(const float4*)(beta + bb*KS + kk)
                             : make_float4(0.f,0.f,0.f,0.f);
        bW[q*2]   = pk_bf16(v.x, v.y);
        bW[q*2+1] = pk_bf16(v.z, v.w);
    }

    float acc[2][4][4];
    #pragma unroll
    for (int mi = 0; mi < 2; mi++)
        #pragma unroll
        for (int ni = 0; ni < 4; ni++)
            #pragma unroll
            for (int e = 0; e < 4; e++) acc[mi][ni][e] = 0.f;

    for (int t = 0; t < NT2; t++) {
        int buf = t & 1;
        {
            uint32_t* Ar = &As[buf][ra*20 + ha*8];
            *(uint4*)(Ar)     = make_uint4(aW[0], aW[1], aW[2], aW[3]);
            *(uint4*)(Ar + 4) = make_uint4(aW[4], aW[5], aW[6], aW[7]);
            *(uint4*)&Bs[buf][bb*20 + kq*4] = make_uint4(bW[0], bW[1], bW[2], bW[3]);
        }
        __syncthreads();
        if (t + 1 < NT2) {
            int k0 = (t+1) * KT;
            #pragma unroll
            for (int q = 0; q < 4; q++) {
                int kk = k0 + ha*16 + q*4;
                float4 v = (rowokA && kk < KS) ? *(const float4*)(srowA + kk)
                                               : make_float4(0.f,0.f,0.f,0.f);
                aW[q*2]   = pk_bf16(v.x, v.y);
                aW[q*2+1] = pk_bf16(v.z, v.w);
            }
            #pragma unroll
            for (int q = 0; q < 2; q++) {
                int kk = k0 + kq*8 + q*4;
                float4 v = (kk < KS) ? *(const float4*)(beta + bb*KS + kk)
                                     : make_float4(0.f,0.f,0.f,0.f);
                bW[q*2]   = pk_bf16(v.x, v.y);
                bW[q*2+1] = pk_bf16(v.z, v.w);
            }
        }
        uint32_t bufA = buf * (ABUF_W*4);
        uint32_t bufB = buf * (BBUF_W*4);
        #pragma unroll
        for (int p = 0; p < 2; p++) {
            uint32_t aF[2][4], bF[2][4];
            ldsm4(aF[0], addrA[0] + bufA + p*32);
            ldsm4(aF[1], addrA[1] + bufA + p*32);
            ldsm4(bF[0], addrB[0] + bufB + p*32);
            ldsm4(bF[1], addrB[1] + bufB + p*32);
            #pragma unroll
            for (int mi = 0; mi < 2; mi++) {
                mma_bf16(acc[mi][0], aF[mi], &bF[0][0]);
                mma_bf16(acc[mi][1], aF[mi], &bF[0][2]);
                mma_bf16(acc[mi][2], aF[mi], &bF[1][0]);
                mma_bf16(acc[mi][3], aF[mi], &bF[1][2]);
            }
        }
        __syncthreads();
    }

    #pragma unroll
    for (int mi = 0; mi < 2; mi++) {
        int rowa = row0 + wm*32 + mi*16 + gid;
        int rowb = rowa + 8;
        #pragma unroll
        for (int ni = 0; ni < 4; ni++) {
            int col = wn*32 + ni*8 + tg*2;
            if (rowa < M_ROWS) {
                float t = vt[rowa];
                float2 o = make_float2(acc[mi][ni][0] + t, acc[mi][ni][1] + t);
                *(float2*)&g_vshaped[(size_t)rowa*64 + col] = o;
            }
            if (rowb < M_ROWS) {
                float t = vt[rowb];
                float2 o = make_float2(acc[mi][ni][2] + t, acc[mi][ni][3] + t);
                *(float2*)&g_vshaped[(size_t)rowb*64 + col] = o;
            }
        }
    }
}

// ---------------- K5a: pose-blend GEMM from preconverted g_pdw ----------------
#define NT5 7   // 7 x 16 words = 112 = PDW
__global__ __launch_bounds__(256, 3) void k_posegemm() {
    __shared__ uint32_t As[2][ABUF_W];
    __shared__ uint32_t Bs[2][BBUF_W];
    int tid = threadIdx.x;
    int warp = tid >> 5, lane = tid & 31;
    int gid = lane >> 2, tg = lane & 3;
    int wm = warp >> 1, wn = warp & 1;
    int row0 = blockIdx.x * 128;

    int ra = tid >> 1, ha = tid & 1;
    bool rowokA = (row0 + ra) < M_ROWS;
    const uint32_t* arow = g_pdw + (size_t)(rowokA ? (row0 + ra) : 0) * PDW + ha*8;
    int bb = tid >> 2, kq = tid & 3;

    uint32_t addrA[2], addrB[2];
    {
        int rA = (lane & 7) + (lane & 8);
        int wA = (lane & 16) >> 2;
        addrA[0] = smem_u32(&As[0][(wm*32 + 0*16 + rA)*20 + wA]);
        addrA[1] = smem_u32(&As[0][(wm*32 + 1*16 + rA)*20 + wA]);
        int nB0 = wn*32 + ((lane & 16) >> 1) + (lane & 7);
        int wB = (lane & 8) >> 1;
        addrB[0] = smem_u32(&Bs[0][nB0*20 + wB]);
        addrB[1] = smem_u32(&Bs[0][(nB0 + 16)*20 + wB]);
    }

    uint4 aV0, aV1;
    uint32_t bW[4];
    aV0 = rowokA ? *(const uint4*)(arow)     : make_uint4(0,0,0,0);
    aV1 = rowokA ? *(const uint4*)(arow + 4) : make_uint4(0,0,0,0);
    #pragma unroll
    for (int i = 0; i < 4; i++) {
        int kk = kq*8 + i*2;
        float f0 = (kk   < KP) ? g_lrot[bb*KP + kk]     : 0.f;
        float f1 = (kk+1 < KP) ? g_lrot[bb*KP + kk + 1] : 0.f;
        bW[i] = pk_bf16(f0, f1);
    }

    float acc[2][4][4];
    #pragma unroll
    for (int mi = 0; mi < 2; mi++)
        #pragma unroll
        for (int ni = 0; ni < 4; ni++)
            #pragma unroll
            for (int e = 0; e < 4; e++) acc[mi][ni][e] = 0.f;

    for (int t = 0; t < NT5; t++) {
        int buf = t & 1;
        {
            uint32_t* Ar = &As[buf][ra*20 + ha*8];
            *(uint4*)(Ar)     = aV0;
            *(uint4*)(Ar + 4) = aV1;
            *(uint4*)&Bs[buf][bb*20 + kq*4] = make_uint4(bW[0], bW[1], bW[2], bW[3]);
        }
        __syncthreads();
        if (t + 1 < NT5) {
            int w0 = (t+1) * 16;
            aV0 = rowokA ? *(const uint4*)(arow + w0)     : make_uint4(0,0,0,0);
            aV1 = rowokA ? *(const uint4*)(arow + w0 + 4) : make_uint4(0,0,0,0);
            #pragma unroll
            for (int i = 0; i < 4; i++) {
                int kk = (t+1)*KT + kq*8 + i*2;
                float f0 = (kk   < KP) ? g_lrot[bb*KP + kk]     : 0.f;
                float f1 = (kk+1 < KP) ? g_lrot[bb*KP + kk + 1] : 0.f;
                bW[i] = pk_bf16(f0, f1);
            }
        }
        uint32_t bufA = buf * (ABUF_W*4);
        uint32_t bufB = buf * (BBUF_W*4);
        #pragma unroll
        for (int p = 0; p < 2; p++) {
            uint32_t aF[2][4], bF[2][4];
            ldsm4(aF[0], addrA[0] + bufA + p*32);
            ldsm4(aF[1], addrA[1] + bufA + p*32);
            ldsm4(bF[0], addrB[0] + bufB + p*32);
            ldsm4(bF[1], addrB[1] + bufB + p*32);
            #pragma unroll
            for (int mi = 0; mi < 2; mi++) {
                mma_bf16(acc[mi][0], aF[mi], &bF[0][0]);
                mma_bf16(acc[mi][1], aF[mi], &bF[0][2]);
                mma_bf16(acc[mi][2], aF[mi], &bF[1][0]);
                mma_bf16(acc[mi][3], aF[mi], &bF[1][2]);
            }
        }
        __syncthreads();
    }

    // epilogue: v_posed = acc + v_shaped -> g_vposed
    #pragma unroll
    for (int mi = 0; mi < 2; mi++) {
        int rowa = row0 + wm*32 + mi*16 + gid;
        int rowb = rowa + 8;
        #pragma unroll
        for (int ni = 0; ni < 4; ni++) {
            int col = wn*32 + ni*8 + tg*2;
            if (rowa < M_ROWS) {
                float2 vs = *(const float2*)&g_vshaped[(size_t)rowa*64 + col];
                float2 o = make_float2(acc[mi][ni][0] + vs.x, acc[mi][ni][1] + vs.y);
                *(float2*)&g_vposed[(size_t)rowa*64 + col] = o;
            }
            if (rowb < M_ROWS) {
                float2 vs = *(const float2*)&g_vshaped[(size_t)rowb*64 + col];
                float2 o = make_float2(acc[mi][ni][2] + vs.x, acc[mi][ni][3] + vs.y);
                *(float2*)&g_vposed[(size_t)rowb*64 + col] = o;
            }
        }
    }
}

// ---------------- K3: J split-K partials ----------------
__global__ __launch_bounds__(192) void k_joints(const float* __restrict__ Jr) {
    __shared__ float vsS[192*36];
    __shared__ float jrS[24*32];
    int tid = threadIdx.x;
    int bcol = tid & 63, d = tid >> 6;
    float acc[24];
    #pragma unroll
    for (int j = 0; j < 24; j++) acc[j] = 0.f;

    int nchunks = (NV + 31) / 32;
    for (int c = blockIdx.x; c < nchunks; c += gridDim.x) {
        int v0 = c * 32;
        int base = 3 * v0 * 64;
        #pragma unroll
        for (int q = 0; q < 32; q++) {
            int gi = base + q*192 + tid;
            vsS[tid*36 + q] = (gi < M_ROWS*64) ? g_vshaped[gi] : 0.f;
        }
        for (int i = tid; i < 768; i += 192) {
            int j = i >> 5, k = i & 31;
            jrS[i] = (v0 + k < NV) ? Jr[j*NV + v0 + k] : 0.f;
        }
        __syncthreads();
        #pragma unroll
        for (int kk = 0; kk < 8; kk++) {
            float4 v4 = *(float4*)&vsS[tid*36 + kk*4];
            #pragma unroll
            for (int j = 0; j < 24; j++) {
                float4 j4 = *(float4*)&jrS[j*32 + kk*4];
                acc[j] = fmaf(v4.x, j4.x, acc[j]);
                acc[j] = fmaf(v4.y, j4.y, acc[j]);
                acc[j] = fmaf(v4.z, j4.z, acc[j]);
                acc[j] = fmaf(v4.w, j4.w, acc[j]);
            }
        }
        __syncthreads();
    }
    #pragma unroll
    for (int j = 0; j < 24; j++)
        g_Jpart[blockIdx.x*4608 + bcol*72 + j*3 + d] = acc[j];
}

// ---------------- K3b: reduce J partials ----------------
__global__ __launch_bounds__(256) void k_joints_reduce() {
    __shared__ float part[8][32];
    int idx = blockIdx.x * 32 + (threadIdx.x & 31);
    int seg = threadIdx.x >> 5;
    float s = 0.f;
    #pragma unroll
    for (int q = 0; q < 32; q++) {
        int blk = seg*32 + q;
        s += g_Jpart[blk*4608 + idx];
    }
    part[seg][threadIdx.x & 31] = s;
    __syncthreads();
    if (seg == 0) {
        float t = part[0][threadIdx.x & 31];
        #pragma unroll
        for (int q = 1; q < 8; q++) t += part[q][threadIdx.x & 31];
        g_J[idx] = t;
    }
}

// ---------------- K4: kinematic chain -> pair-packed G ----------------
__global__ void k_chain() {
    int b = blockIdx.x, lane = threadIdx.x;
    __shared__ float G[24][12];
    __shared__ float R[24][9];
    __shared__ float Jv[24][3];
    for (int i = lane; i < 216; i += 32) R[i/9][i%9] = g_R[b*216 + i];
    for (int i = lane; i < 72; i += 32) Jv[i/3][i%3] = g_J[b*72 + i];
    __syncwarp();
    for (int j = 0; j < 24; j++) {
        float val = 0.f;
        int m = lane >> 2, n = lane & 3;
        if (lane < 12) {
            if (j == 0) {
                val = (n < 3) ? R[0][m*3 + n] : Jv[0][m];
            } else {
                int p = c_parent[j-1];
                if (n < 3) {
                    val = G[p][m*4+0]*R[j][n] + G[p][m*4+1]*R[j][3+n] + G[p][m*4+2]*R[j][6+n];
                } else {
                    float t0 = Jv[j][0] - Jv[p][0];
                    float t1 = Jv[j][1] - Jv[p][1];
                    float t2 = Jv[j][2] - Jv[p][2];
                    val = G[p][m*4+0]*t0 + G[p][m*4+1]*t1 + G[p][m*4+2]*t2 + G[p][m*4+3];
                }
            }
        }
        __syncwarp();
        if (lane < 12) G[j][lane] = val;
        __syncwarp();
    }
    for (int i = lane; i < 72; i += 32) {
        int j = i / 3, m = i % 3;
        float c = G[j][m*4+0]*Jv[j][0] + G[j][m*4+1]*Jv[j][1] + G[j][m*4+2]*Jv[j][2];
        G[j][m*4+3] -= c;
    }
    __syncwarp();
    for (int i = lane; i < 288; i += 32)
        g_Gpair[(b>>1)*576 + i*2 + (b&1)] = G[i/12][i%12];
}

// ---------------- K5b: skinning, 4 vertices/thread, f32x2, direct stores ----------------
#define GST 580
__global__ __launch_bounds__(256) void k_skin(const float* __restrict__ wts,
                                              float* __restrict__ out) {
    __shared__ float Gs[8*GST];
    __shared__ float ws[128*25];
    int tid = threadIdx.x;
    int vt0 = blockIdx.x * 128;
    int g = blockIdx.y;

    for (int i = tid; i < 8*144; i += 256) {
        int bpg = i / 144, q = i % 144;
        *(float4*)&Gs[bpg*GST + q*4] =
            *(const float4*)&g_Gpair[(g*8 + bpg)*576 + q*4];
    }
    for (int i = tid; i < 128*24; i += 256) {
        int vl = i / 24, j = i % 24;
        int v = vt0 + vl;
        ws[vl*25 + j] = (v < NV) ? wts[(size_t)v*24 + j] : 0.f;
    }
    __syncthreads();

    int bpg = tid & 7;
    int vg = tid >> 3;
    int vl0 = vg * 4;
    int bp = g*8 + bpg;

    ull xv[4], yv[4], zv[4];
    #pragma unroll
    for (int i = 0; i < 4; i++) {
        int v = vt0 + vl0 + i;
        int vc = (v < NV) ? v : (NV - 1);
        xv[i] = *(const ull*)&g_vposed[(size_t)(vc*3 + 0)*64 + 2*bp];
        yv[i] = *(const ull*)&g_vposed[(size_t)(vc*3 + 1)*64 + 2*bp];
        zv[i] = *(const ull*)&g_vposed[(size_t)(vc*3 + 2)*64 + 2*bp];
    }

    ull o0[4], o1[4], o2[4];
    #pragma unroll
    for (int i = 0; i < 4; i++) { o0[i] = 0ull; o1[i] = 0ull; o2[i] = 0ull; }

    const float* Gb = &Gs[bpg*GST];
    #pragma unroll
    for (int j = 0; j < 24; j++) {
        ulonglong2 q0 = *(const ulonglong2*)&Gb[(j*12 + 0)*2];
        ulonglong2 q1 = *(const ulonglong2*)&Gb[(j*12 + 2)*2];
        ulonglong2 q2 = *(const ulonglong2*)&Gb[(j*12 + 4)*2];
        ulonglong2 q3 = *(const ulonglong2*)&Gb[(j*12 + 6)*2];
        ulonglong2 q4 = *(const ulonglong2*)&Gb[(j*12 + 8)*2];
        ulonglong2 q5 = *(const ulonglong2*)&Gb[(j*12 + 10)*2];
        #pragma unroll
        for (int i = 0; i < 4; i++) {
            float wj = ws[(vl0 + i)*25 + j];
            ull w2 = pk2(wj, wj);
            ull r0 = q1.y;
            fma2(r0, q0.x, xv[i]); fma2(r0, q0.y, yv[i]); fma2(r0, q1.x, zv[i]);
            fma2(o0[i], w2, r0);
            ull r1 = q3.y;
            fma2(r1, q2.x, xv[i]); fma2(r1, q2.y, yv[i]); fma2(r1, q3.x, zv[i]);
            fma2(o1[i], w2, r1);
            ull r2 = q5.y;
            fma2(r2, q4.x, xv[i]); fma2(r2, q4.y, yv[i]); fma2(r2, q5.x, zv[i]);
            fma2(o2[i], w2, r2);
        }
    }

    int v0g = vt0 + vl0;
    if (v0g + 3 < NV) {
        float vb0[12], vb1[12];
        #pragma unroll
        for (int i = 0; i < 4; i++) {
            unpk2(vb0[i*3 + 0], vb1[i*3 + 0], o0[i]);
            unpk2(vb0[i*3 + 1], vb1[i*3 + 1], o1[i]);
            unpk2(vb0[i*3 + 2], vb1[i*3 + 2], o2[i]);
        }
        size_t ob0 = (size_t)(2*bp)     * M_ROWS + (size_t)v0g * 3;
        size_t ob1 = (size_t)(2*bp + 1) * M_ROWS + (size_t)v0g * 3;
        *(float4*)&out[ob0 + 0] = make_float4(vb0[0], vb0[1], vb0[2],  vb0[3]);
        *(float4*)&out[ob0 + 4] = make_float4(vb0[4], vb0[5], vb0[6],  vb0[7]);
        *(float4*)&out[ob0 + 8] = make_float4(vb0[8], vb0[9], vb0[10], vb0[11]);
        *(float4*)&out[ob1 + 0] = make_float4(vb1[0], vb1[1], vb1[2],  vb1[3]);
        *(float4*)&out[ob1 + 4] = make_float4(vb1[4], vb1[5], vb1[6],  vb1[7]);
        *(float4*)&out[ob1 + 8] = make_float4(vb1[8], vb1[9], vb1[10], vb1[11]);
    }
}

extern "C" void kernel_launch(void* const* d_in, const int* in_sizes, int n_in,
                              void* d_out, int out_size) {
    const float* pose = (const float*)d_in[0];
    const float* beta = (const float*)d_in[1];
    const float* vt   = (const float*)d_in[2];
    const float* sd   = (const float*)d_in[3];
    const float* pd   = (const float*)d_in[4];
    const float* Jr   = (const float*)d_in[5];
    const float* wts  = (const float*)d_in[6];
    float* out = (float*)d_out;

    int nblk = (M_ROWS + 127) / 128;
    k_pdcvt<<<(M_ROWS*PDW + 255)/256, 256>>>(pd);   // 1
    k_pose<<<NB, 32>>>(pose);                        // 2
    k_shape<<<nblk, 256>>>(sd, beta, vt);            // 3
    k_posegemm<<<nblk, 256>>>();                     // 4 <- profiler slot
    k_joints<<<NBLK_J, 192>>>(Jr);                   // 5 (reads g_vshaped, untouched)
    k_joints_reduce<<<144, 256>>>();                 // 6
    k_chain<<<NB, 32>>>();                           // 7
    k_skin<<<dim3((NV + 127)/128, 4), 256>>>(wts, out); // 8
}

// round 16
// speedup vs baseline: 1.0864x; 1.0864x over previous
#include <cuda_runtime.h>
#include <cuda_bf16.h>
#include <math.h>
#include <stdint.h>

#define NB 64
#define NV 50000
#define M_ROWS (NV*3)   // 150000
#define KS 300
#define KP 207
#define PDW 112         // padded posedirs row length in bf16-pair words

typedef unsigned long long ull;

__constant__ int c_parent[23] = {0,0,0,1,2,3,4,5,6,7,8,9,9,9,12,13,14,16,17,18,19,20,21};

// Scratch (device globals; no allocation allowed)
__device__ float g_R[NB*24*9];
__device__ float g_lrot[NB*KP];
__device__ float g_vshaped[M_ROWS*NB];     // [row][b]
__device__ float g_vposed[M_ROWS*NB];      // [row][b]
__device__ float g_J[NB*72];
__device__ float g_Gpair[NB*288];          // pair-packed G
__device__ uint32_t g_pdw[M_ROWS*PDW];     // posedirs as bf16-pair words, padded
#define NBLK_J 256
__device__ float g_Jpart[NBLK_J*4608];

// -------- helpers --------
__device__ __forceinline__ uint32_t pk_bf16(float lo, float hi) {
    __nv_bfloat162 h = __floats2bfloat162_rn(lo, hi);
    return *(uint32_t*)&h;
}
__device__ __forceinline__ uint32_t smem_u32(const void* p) {
    return (uint32_t)__cvta_generic_to_shared(p);
}
__device__ __forceinline__ void ldsm4(uint32_t* r, uint32_t addr) {
    asm volatile("ldmatrix.sync.aligned.m8n8.x4.shared.b16 {%0,%1,%2,%3}, [%4];"
        : "=r"(r[0]), "=r"(r[1]), "=r"(r[2]), "=r"(r[3]) : "r"(addr));
}
__device__ __forceinline__ void mma_bf16(float* d,
                                         const uint32_t* a,
                                         const uint32_t* b) {
    asm volatile(
        "mma.sync.aligned.m16n8k16.row.col.f32.bf16.bf16.f32 "
        "{%0,%1,%2,%3}, {%4,%5,%6,%7}, {%8,%9}, {%0,%1,%2,%3};\n"
        : "+f"(d[0]), "+f"(d[1]), "+f"(d[2]), "+f"(d[3])
        : "r"(a[0]), "r"(a[1]), "r"(a[2]), "r"(a[3]),
          "r"(b[0]), "r"(b[1]));
}
__device__ __forceinline__ ull pk2(float lo, float hi) {
    ull r;
    asm("mov.b64 %0, {%1,%2};" : "=l"(r) : "f"(lo), "f"(hi));
    return r;
}
__device__ __forceinline__ void fma2(ull& d, ull a, ull b) {
    asm("fma.rn.f32x2 %0, %1, %2, %0;" : "+l"(d) : "l"(a), "l"(b));
}
__device__ __forceinline__ void unpk2(float& lo, float& hi, ull v) {
    asm("mov.b64 {%0,%1}, %2;" : "=f"(lo), "=f"(hi) : "l"(v));
}

// ---------------- K0: posedirs fp32 -> bf16-pair words (uint4 stores) ----------------
__global__ __launch_bounds__(256) void k_pdcvt(const float* __restrict__ pd) {
    int idx = blockIdx.x * 256 + threadIdx.x;     // one uint4 (8 floats) per thread
    if (idx < M_ROWS * (PDW/4)) {
        int r = idx / (PDW/4), c4 = idx % (PDW/4);
        int k0 = c4 * 8;
        const float* src = pd + (size_t)r * KP;
        uint32_t w[4];
        #pragma unroll
        for (int i = 0; i < 4; i++) {
            int k = k0 + 2*i;
            float f0 = (k   < KP) ? src[k]     : 0.f;
            float f1 = (k+1 < KP) ? src[k + 1] : 0.f;
            w[i] = pk_bf16(f0, f1);
        }
        *(uint4*)&g_pdw[(size_t)r*PDW + c4*4] = make_uint4(w[0], w[1], w[2], w[3]);
    }
}

// ---------------- K1: rodrigues -> R, lrotmin ----------------
__global__ void k_pose(const float* __restrict__ pose) {
    int b = blockIdx.x;
    int j = threadIdx.x;
    if (j < 24) {
        float t0 = pose[b*72 + j*3 + 0];
        float t1 = pose[b*72 + j*3 + 1];
        float t2 = pose[b*72 + j*3 + 2];
        float a0 = t0 + 1e-8f, a1 = t1 + 1e-8f, a2 = t2 + 1e-8f;
        float ang = sqrtf(a0*a0 + a1*a1 + a2*a2);
        float inv = 1.0f/ang;
        float half = 0.5f*ang;
        float s = sinf(half), c = cosf(half);
        float qw = c, qx = s*t0*inv, qy = s*t1*inv, qz = s*t2*inv;
        float qn = rsqrtf(qw*qw + qx*qx + qy*qy + qz*qz);
        qw *= qn; qx *= qn; qy *= qn; qz *= qn;
        float R[9];
        R[0] = qw*qw + qx*qx - qy*qy - qz*qz;
        R[1] = 2.f*(qx*qy - qw*qz);
        R[2] = 2.f*(qw*qy + qx*qz);
        R[3] = 2.f*(qw*qz + qx*qy);
        R[4] = qw*qw - qx*qx + qy*qy - qz*qz;
        R[5] = 2.f*(qy*qz - qw*qx);
        R[6] = 2.f*(qx*qz - qw*qy);
        R[7] = 2.f*(qw*qx + qy*qz);
        R[8] = qw*qw - qx*qx - qy*qy + qz*qz;
        #pragma unroll
        for (int e = 0; e < 9; e++) g_R[b*216 + j*9 + e] = R[e];
        if (j >= 1) {
            #pragma unroll
            for (int e = 0; e < 9; e++) {
                float d = (e == 0 || e == 4 || e == 8) ? 1.0f : 0.0f;
                g_lrot[b*207 + (j-1)*9 + e] = R[e] - d;
            }
        }
    }
}

// ---------------- K2: v_shaped GEMM, bf16 MMA + ldmatrix ----------------
#define KT 32
#define NT2 ((KS + KT - 1) / KT)   // 10
#define ABUF_W (128*20)
#define BBUF_W (64*20)
__global__ __launch_bounds__(256, 2) void k_shape(const float* __restrict__ sd,
                                                  const float* __restrict__ beta,
                                                  const float* __restrict__ vt) {
    __shared__ uint32_t As[2][ABUF_W];
    __shared__ uint32_t Bs[2][BBUF_W];
    int tid = threadIdx.x;
    int warp = tid >> 5, lane = tid & 31;
    int gid = lane >> 2, tg = lane & 3;
    int wm = warp >> 1, wn = warp & 1;
    int row0 = blockIdx.x * 128;

    int ra = tid >> 1, ha = tid & 1;
    bool rowokA = (row0 + ra) < M_ROWS;
    const float* srowA = sd + (size_t)(rowokA ? (row0 + ra) : 0) * KS;
    int bb = tid >> 2, kq = tid & 3;

    uint32_t addrA[2], addrB[2];
    {
        int rA = (lane & 7) + (lane & 8);
        int wA = (lane & 16) >> 2;
        addrA[0] = smem_u32(&As[0][(wm*32 + 0*16 + rA)*20 + wA]);
        addrA[1] = smem_u32(&As[0][(wm*32 + 1*16 + rA)*20 + wA]);
        int nB0 = wn*32 + ((lane & 16) >> 1) + (lane & 7);
        int wB = (lane & 8) >> 1;
        addrB[0] = smem_u32(&Bs[0][nB0*20 + wB]);
        addrB[1] = smem_u32(&Bs[0][(nB0 + 16)*20 + wB]);
    }

    uint32_t aW[8], bW[4];
    #pragma unroll
    for (int q = 0; q < 4; q++) {
        int kk = ha*16 + q*4;
        float4 v = (rowokA && kk < KS) ? *(const float4*)(srowA + kk)
                                       : make_float4(0.f,0.f,0.f,0.f);
        aW[q*2]   = pk_bf16(v.x, v.y);
        aW[q*2+1] = pk_bf16(v.z, v.w);
    }
    #pragma unroll
    for (int q = 0; q < 2; q++) {
        int kk = kq*8 + q*4;
        float4 v = (kk < KS) ? *(const float4*)(beta + bb*KS + kk)
                             : make_float4(0.f,0.f,0.f,0.f);
        bW[q*2]   = pk_bf16(v.x, v.y);
        bW[q*2+1] = pk_bf16(v.z, v.w);
    }

    float acc[2][4][4];
    #pragma unroll
    for (int mi = 0; mi < 2; mi++)
        #pragma unroll
        for (int ni = 0; ni < 4; ni++)
            #pragma unroll
            for (int e = 0; e < 4; e++) acc[mi][ni][e] = 0.f;

    for (int t = 0; t < NT2; t++) {
        int buf = t & 1;
        {
            uint32_t* Ar = &As[buf][ra*20 + ha*8];
            *(uint4*)(Ar)     = make_uint4(aW[0], aW[1], aW[2], aW[3]);
            *(uint4*)(Ar + 4) = make_uint4(aW[4], aW[5], aW[6], aW[7]);
            *(uint4*)&Bs[buf][bb*20 + kq*4] = make_uint4(bW[0], bW[1], bW[2], bW[3]);
        }
        __syncthreads();
        if (t + 1 < NT2) {
            int k0 = (t+1) * KT;
            #pragma unroll
            for (int q = 0; q < 4; q++) {
                int kk = k0 + ha*16 + q*4;
                float4 v = (rowokA && kk < KS) ? *(const float4*)(srowA + kk)
                                               : make_float4(0.f,0.f,0.f,0.f);
                aW[q*2]   = pk_bf16(v.x, v.y);
                aW[q*2+1] = pk_bf16(v.z, v.w);
            }
            #pragma unroll
            for (int q = 0; q < 2; q++) {
                int kk = k0 + kq*8 + q*4;
                float4 v = (kk < KS) ? *(const float4*)(beta + bb*KS + kk)
                                     : make_float4(0.f,0.f,0.f,0.f);
                bW[q*2]   = pk_bf16(v.x, v.y);
                bW[q*2+1] = pk_bf16(v.z, v.w);
            }
        }
        uint32_t bufA = buf * (ABUF_W*4);
        uint32_t bufB = buf * (BBUF_W*4);
        #pragma unroll
        for (int p = 0; p < 2; p++) {
            uint32_t aF[2][4], bF[2][4];
            ldsm4(aF[0], addrA[0] + bufA + p*32);
            ldsm4(aF[1], addrA[1] + bufA + p*32);
            ldsm4(bF[0], addrB[0] + bufB + p*32);
            ldsm4(bF[1], addrB[1] + bufB + p*32);
            #pragma unroll
            for (int mi = 0; mi < 2; mi++) {
                mma_bf16(acc[mi][0], aF[mi], &bF[0][0]);
                mma_bf16(acc[mi][1], aF[mi], &bF[0][2]);
                mma_bf16(acc[mi][2], aF[mi], &bF[1][0]);
                mma_bf16(acc[mi][3], aF[mi], &bF[1][2]);
            }
        }
        __syncthreads();
    }

    #pragma unroll
    for (int mi = 0; mi < 2; mi++) {
        int rowa = row0 + wm*32 + mi*16 + gid;
        int rowb = rowa + 8;
        #pragma unroll
        for (int ni = 0; ni < 4; ni++) {
            int col = wn*32 + ni*8 + tg*2;
            if (rowa < M_ROWS) {
                float t = vt[rowa];
                float2 o = make_float2(acc[mi][ni][0] + t, acc[mi][ni][1] + t);
                *(float2*)&g_vshaped[(size_t)rowa*64 + col] = o;
            }
            if (rowb < M_ROWS) {
                float t = vt[rowb];
                float2 o = make_float2(acc[mi][ni][2] + t, acc[mi][ni][3] + t);
                *(float2*)&g_vshaped[(size_t)rowb*64 + col] = o;
            }
        }
    }
}

// ---------------- K3: J split-K partials (conflict-free staging) ----------------
// vsS2[96][68]: batch-contiguous rows (float4 stage, scalar conflict-free compute reads)
// jrT[32][28]:  transposed Jr chunk (float4 broadcast reads over j)
__global__ __launch_bounds__(192) void k_joints(const float* __restrict__ Jr) {
    __shared__ float vsS2[96*68];
    __shared__ float jrT[32*28];
    int tid = threadIdx.x;
    int bcol = tid & 63, d = tid >> 6;
    float acc[24];
    #pragma unroll
    for (int j = 0; j < 24; j++) acc[j] = 0.f;

    int nchunks = (NV + 31) / 32;   // 1563
    for (int c = blockIdx.x; c < nchunks; c += gridDim.x) {
        int v0 = c * 32;
        int r0 = 3 * v0;
        // stage v_shaped rows [r0, r0+96) x 64 batches, float4
        #pragma unroll
        for (int s = 0; s < 8; s++) {
            int i = tid + s*192;            // 0..1535
            int row = i >> 4, ch = i & 15;
            float4 v = make_float4(0.f,0.f,0.f,0.f);
            if (r0 + row < M_ROWS)
                v = *(const float4*)&g_vshaped[(size_t)(r0 + row)*64 + ch*4];
            *(float4*)&vsS2[row*68 + ch*4] = v;
        }
        // stage Jr transposed: jrT[k][j]
        #pragma unroll
        for (int s = 0; s < 4; s++) {
            int i = tid + s*192;            // 0..767
            int k = i / 24, j = i % 24;
            jrT[k*28 + j] = (v0 + k < NV) ? Jr[(size_t)j*NV + v0 + k] : 0.f;
        }
        __syncthreads();
        #pragma unroll
        for (int k = 0; k < 32; k++) {
            float vx = vsS2[(3*k + d)*68 + bcol];
            #pragma unroll
            for (int jj = 0; jj < 6; jj++) {
                float4 j4 = *(const float4*)&jrT[k*28 + jj*4];
                acc[jj*4+0] = fmaf(vx, j4.x, acc[jj*4+0]);
                acc[jj*4+1] = fmaf(vx, j4.y, acc[jj*4+1]);
                acc[jj*4+2] = fmaf(vx, j4.z, acc[jj*4+2]);
                acc[jj*4+3] = fmaf(vx, j4.w, acc[jj*4+3]);
            }
        }
        __syncthreads();
    }
    #pragma unroll
    for (int j = 0; j < 24; j++)
        g_Jpart[blockIdx.x*4608 + bcol*72 + j*3 + d] = acc[j];
}

// ---------------- K3b: reduce J partials ----------------
__global__ __launch_bounds__(256) void k_joints_reduce() {
    __shared__ float part[8][32];
    int idx = blockIdx.x * 32 + (threadIdx.x & 31);
    int seg = threadIdx.x >> 5;
    float s = 0.f;
    #pragma unroll
    for (int q = 0; q < 32; q++) {
        int blk = seg*32 + q;
        s += g_Jpart[blk*4608 + idx];
    }
    part[seg][threadIdx.x & 31] = s;
    __syncthreads();
    if (seg == 0) {
        float t = part[0][threadIdx.x & 31];
        #pragma unroll
        for (int q = 1; q < 8; q++) t += part[q][threadIdx.x & 31];
        g_J[idx] = t;
    }
}

// ---------------- K4: kinematic chain -> pair-packed G ----------------
__global__ void k_chain() {
    int b = blockIdx.x, lane = threadIdx.x;
    __shared__ float G[24][12];
    __shared__ float R[24][9];
    __shared__ float Jv[24][3];
    for (int i = lane; i < 216; i += 32) R[i/9][i%9] = g_R[b*216 + i];
    for (int i = lane; i < 72; i += 32) Jv[i/3][i%3] = g_J[b*72 + i];
    __syncwarp();
    for (int j = 0; j < 24; j++) {
        float val = 0.f;
        int m = lane >> 2, n = lane & 3;
        if (lane < 12) {
            if (j == 0) {
                val = (n < 3) ? R[0][m*3 + n] : Jv[0][m];
            } else {
                int p = c_parent[j-1];
                if (n < 3) {
                    val = G[p][m*4+0]*R[j][n] + G[p][m*4+1]*R[j][3+n] + G[p][m*4+2]*R[j][6+n];
                } else {
                    float t0 = Jv[j][0] - Jv[p][0];
                    float t1 = Jv[j][1] - Jv[p][1];
                    float t2 = Jv[j][2] - Jv[p][2];
                    val = G[p][m*4+0]*t0 + G[p][m*4+1]*t1 + G[p][m*4+2]*t2 + G[p][m*4+3];
                }
            }
        }
        __syncwarp();
        if (lane < 12) G[j][lane] = val;
        __syncwarp();
    }
    for (int i = lane; i < 72; i += 32) {
        int j = i / 3, m = i % 3;
        float c = G[j][m*4+0]*Jv[j][0] + G[j][m*4+1]*Jv[j][1] + G[j][m*4+2]*Jv[j][2];
        G[j][m*4+3] -= c;
    }
    __syncwarp();
    for (int i = lane; i < 288; i += 32)
        g_Gpair[(b>>1)*576 + i*2 + (b&1)] = G[i/12][i%12];
}

// ---------------- K5a: pose-blend GEMM from preconverted g_pdw ----------------
#define NT5 7
__global__ __launch_bounds__(256, 3) void k_posegemm() {
    __shared__ uint32_t As[2][ABUF_W];
    __shared__ uint32_t Bs[2][BBUF_W];
    int tid = threadIdx.x;
    int warp = tid >> 5, lane = tid & 31;
    int gid = lane >> 2, tg = lane & 3;
    int wm = warp >> 1, wn = warp & 1;
    int row0 = blockIdx.x * 128;

    int ra = tid >> 1, ha = tid & 1;
    bool rowokA = (row0 + ra) < M_ROWS;
    const uint32_t* arow = g_pdw + (size_t)(rowokA ? (row0 + ra) : 0) * PDW + ha*8;
    int bb = tid >> 2, kq = tid & 3;

    uint32_t addrA[2], addrB[2];
    {
        int rA = (lane & 7) + (lane & 8);
        int wA = (lane & 16) >> 2;
        addrA[0] = smem_u32(&As[0][(wm*32 + 0*16 + rA)*20 + wA]);
        addrA[1] = smem_u32(&As[0][(wm*32 + 1*16 + rA)*20 + wA]);
        int nB0 = wn*32 + ((lane & 16) >> 1) + (lane & 7);
        int wB = (lane & 8) >> 1;
        addrB[0] = smem_u32(&Bs[0][nB0*20 + wB]);
        addrB[1] = smem_u32(&Bs[0][(nB0 + 16)*20 + wB]);
    }

    uint4 aV0, aV1;
    uint32_t bW[4];
    aV0 = rowokA ? *(const uint4*)(arow)     : make_uint4(0,0,0,0);
    aV1 = rowokA ? *(const uint4*)(arow + 4) : make_uint4(0,0,0,0);
    #pragma unroll
    for (int i = 0; i < 4; i++) {
        int kk = kq*8 + i*2;
        float f0 = (kk   < KP) ? g_lrot[bb*KP + kk]     : 0.f;
        float f1 = (kk+1 < KP) ? g_lrot[bb*KP + kk + 1] : 0.f;
        bW[i] = pk_bf16(f0, f1);
    }

    float acc[2][4][4];
    #pragma unroll
    for (int mi = 0; mi < 2; mi++)
        #pragma unroll
        for (int ni = 0; ni < 4; ni++)
            #pragma unroll
            for (int e = 0; e < 4; e++) acc[mi][ni][e] = 0.f;

    for (int t = 0; t < NT5; t++) {
        int buf = t & 1;
        {
            uint32_t* Ar = &As[buf][ra*20 + ha*8];
            *(uint4*)(Ar)     = aV0;
            *(uint4*)(Ar + 4) = aV1;
            *(uint4*)&Bs[buf][bb*20 + kq*4] = make_uint4(bW[0], bW[1], bW[2], bW[3]);
        }
        __syncthreads();
        if (t + 1 < NT5) {
            int w0 = (t+1) * 16;
            aV0 = rowokA ? *(const uint4*)(arow + w0)     : make_uint4(0,0,0,0);
            aV1 = rowokA ? *(const uint4*)(arow + w0 + 4) : make_uint4(0,0,0,0);
            #pragma unroll
            for (int i = 0; i < 4; i++) {
                int kk = (t+1)*KT + kq*8 + i*2;
                float f0 = (kk   < KP) ? g_lrot[bb*KP + kk]     : 0.f;
                float f1 = (kk+1 < KP) ? g_lrot[bb*KP + kk + 1] : 0.f;
                bW[i] = pk_bf16(f0, f1);
            }
        }
        uint32_t bufA = buf * (ABUF_W*4);
        uint32_t bufB = buf * (BBUF_W*4);
        #pragma unroll
        for (int p = 0; p < 2; p++) {
            uint32_t aF[2][4], bF[2][4];
            ldsm4(aF[0], addrA[0] + bufA + p*32);
            ldsm4(aF[1], addrA[1] + bufA + p*32);
            ldsm4(bF[0], addrB[0] + bufB + p*32);
            ldsm4(bF[1], addrB[1] + bufB + p*32);
            #pragma unroll
            for (int mi = 0; mi < 2; mi++) {
                mma_bf16(acc[mi][0], aF[mi], &bF[0][0]);
                mma_bf16(acc[mi][1], aF[mi], &bF[0][2]);
                mma_bf16(acc[mi][2], aF[mi], &bF[1][0]);
                mma_bf16(acc[mi][3], aF[mi], &bF[1][2]);
            }
        }
        __syncthreads();
    }

    #pragma unroll
    for (int mi = 0; mi < 2; mi++) {
        int rowa = row0 + wm*32 + mi*16 + gid;
        int rowb = rowa + 8;
        #pragma unroll
        for (int ni = 0; ni < 4; ni++) {
            int col = wn*32 + ni*8 + tg*2;
            if (rowa < M_ROWS) {
                float2 vs = *(const float2*)&g_vshaped[(size_t)rowa*64 + col];
                float2 o = make_float2(acc[mi][ni][0] + vs.x, acc[mi][ni][1] + vs.y);
                *(float2*)&g_vposed[(size_t)rowa*64 + col] = o;
            }
            if (rowb < M_ROWS) {
                float2 vs = *(const float2*)&g_vshaped[(size_t)rowb*64 + col];
                float2 o = make_float2(acc[mi][ni][2] + vs.x, acc[mi][ni][3] + vs.y);
                *(float2*)&g_vposed[(size_t)rowb*64 + col] = o;
            }
        }
    }
}

// ---------------- K5b: skinning, 4 vertices/thread, f32x2, direct stores ----------------
#define GST 580
__global__ __launch_bounds__(256) void k_skin(const float* __restrict__ wts,
                                              float* __restrict__ out) {
    __shared__ float Gs[8*GST];
    __shared__ float ws[128*25];
    int tid = threadIdx.x;
    int vt0 = blockIdx.x * 128;
    int g = blockIdx.y;

    for (int i = tid; i < 8*144; i += 256) {
        int bpg = i / 144, q = i % 144;
        *(float4*)&Gs[bpg*GST + q*4] =
            *(const float4*)&g_Gpair[(g*8 + bpg)*576 + q*4];
    }
    for (int i = tid; i < 128*24; i += 256) {
        int vl = i / 24, j = i % 24;
        int v = vt0 + vl;
        ws[vl*25 + j] = (v < NV) ? wts[(size_t)v*24 + j] : 0.f;
    }
    __syncthreads();

    int bpg = tid & 7;
    int vg = tid >> 3;
    int vl0 = vg * 4;
    int bp = g*8 + bpg;

    ull xv[4], yv[4], zv[4];
    #pragma unroll
    for (int i = 0; i < 4; i++) {
        int v = vt0 + vl0 + i;
        int vc = (v < NV) ? v : (NV - 1);
        xv[i] = *(const ull*)&g_vposed[(size_t)(vc*3 + 0)*64 + 2*bp];
        yv[i] = *(const ull*)&g_vposed[(size_t)(vc*3 + 1)*64 + 2*bp];
        zv[i] = *(const ull*)&g_vposed[(size_t)(vc*3 + 2)*64 + 2*bp];
    }

    ull o0[4], o1[4], o2[4];
    #pragma unroll
    for (int i = 0; i < 4; i++) { o0[i] = 0ull; o1[i] = 0ull; o2[i] = 0ull; }

    const float* Gb = &Gs[bpg*GST];
    #pragma unroll
    for (int j = 0; j < 24; j++) {
        ulonglong2 q0 = *(const ulonglong2*)&Gb[(j*12 + 0)*2];
        ulonglong2 q1 = *(const ulonglong2*)&Gb[(j*12 + 2)*2];
        ulonglong2 q2 = *(const ulonglong2*)&Gb[(j*12 + 4)*2];
        ulonglong2 q3 = *(const ulonglong2*)&Gb[(j*12 + 6)*2];
        ulonglong2 q4 = *(const ulonglong2*)&Gb[(j*12 + 8)*2];
        ulonglong2 q5 = *(const ulonglong2*)&Gb[(j*12 + 10)*2];
        #pragma unroll
        for (int i = 0; i < 4; i++) {
            float wj = ws[(vl0 + i)*25 + j];
            ull w2 = pk2(wj, wj);
            ull r0 = q1.y;
            fma2(r0, q0.x, xv[i]); fma2(r0, q0.y, yv[i]); fma2(r0, q1.x, zv[i]);
            fma2(o0[i], w2, r0);
            ull r1 = q3.y;
            fma2(r1, q2.x, xv[i]); fma2(r1, q2.y, yv[i]); fma2(r1, q3.x, zv[i]);
            fma2(o1[i], w2, r1);
            ull r2 = q5.y;
            fma2(r2, q4.x, xv[i]); fma2(r2, q4.y, yv[i]); fma2(r2, q5.x, zv[i]);
            fma2(o2[i], w2, r2);
        }
    }

    int v0g = vt0 + vl0;
    if (v0g + 3 < NV) {
        float vb0[12], vb1[12];
        #pragma unroll
        for (int i = 0; i < 4; i++) {
            unpk2(vb0[i*3 + 0], vb1[i*3 + 0], o0[i]);
            unpk2(vb0[i*3 + 1], vb1[i*3 + 1], o1[i]);
            unpk2(vb0[i*3 + 2], vb1[i*3 + 2], o2[i]);
        }
        size_t ob0 = (size_t)(2*bp)     * M_ROWS + (size_t)v0g * 3;
        size_t ob1 = (size_t)(2*bp + 1) * M_ROWS + (size_t)v0g * 3;
        *(float4*)&out[ob0 + 0] = make_float4(vb0[0], vb0[1], vb0[2],  vb0[3]);
        *(float4*)&out[ob0 + 4] = make_float4(vb0[4], vb0[5], vb0[6],  vb0[7]);
        *(float4*)&out[ob0 + 8] = make_float4(vb0[8], vb0[9], vb0[10], vb0[11]);
        *(float4*)&out[ob1 + 0] = make_float4(vb1[0], vb1[1], vb1[2],  vb1[3]);
        *(float4*)&out[ob1 + 4] = make_float4(vb1[4], vb1[5], vb1[6],  vb1[7]);
        *(float4*)&out[ob1 + 8] = make_float4(vb1[8], vb1[9], vb1[10], vb1[11]);
    }
}

extern "C" void kernel_launch(void* const* d_in, const int* in_sizes, int n_in,
                              void* d_out, int out_size) {
    const float* pose = (const float*)d_in[0];
    const float* beta = (const float*)d_in[1];
    const float* vt   = (const float*)d_in[2];
    const float* sd   = (const float*)d_in[3];
    const float* pd   = (const float*)d_in[4];
    const float* Jr   = (const float*)d_in[5];
    const float* wts  = (const float*)d_in[6];
    float* out = (float*)d_out;

    int nblk = (M_ROWS + 127) / 128;
    k_pdcvt<<<(M_ROWS*(PDW/4) + 255)/256, 256>>>(pd);   // 1
    k_pose<<<NB, 32>>>(pose);                            // 2
    k_shape<<<nblk, 256>>>(sd, beta, vt);                // 3
    k_joints<<<NBLK_J, 192>>>(Jr);                       // 4 <- profiler slot
    k_posegemm<<<nblk, 256>>>();                         // 5
    k_joints_reduce<<<144, 256>>>();                     // 6
    k_chain<<<NB, 32>>>();                               // 7
    k_skin<<<dim3((NV + 127)/128, 4), 256>>>(wts, out);  // 8
}